// round 11
// baseline (speedup 1.0000x reference)
#include <cuda_runtime.h>
#include <cuda_fp16.h>
#include <math.h>
#include <stdint.h>

// Problem constants
#define BB   4
#define LL   1024
#define DD   768
#define HH   12
#define FF_  3072
#define PP   32
#define MAXD_ 256
#define ML   (BB*LL)   // 4096 rows
#define QKVS 2304      // fused QKV row stride

// ---------------- scratch (device globals; no runtime allocation) ----------
__device__ __half g_qin[ML*DD];
__device__ __half g_QKV[ML*QKVS];
__device__ __half g_Vt[(size_t)BB*HH*64*LL];   // [b][h][d][j]
__device__ __half g_ctx[ML*DD];
__device__ float  g_res1[ML*DD];
__device__ __half g_h2[ML*DD];
__device__ __half g_ff[ML*FF_];
// transposed weights [N,K] fp16
__device__ __half g_WqkvT[QKVS*DD];
__device__ float  g_bqkv[QKVS];
__device__ __half g_WoT[DD*DD];
__device__ __half g_W1T[FF_*DD];
__device__ __half g_W2T[DD*FF_];

// single extern shared symbol for all kernels
extern __shared__ char smem_raw[];

// ======================= helpers =====================
__device__ __forceinline__ uint32_t smem_u32(const void* p) {
    uint32_t a;
    asm("{ .reg .u64 t; cvta.to.shared.u64 t, %1; cvt.u32.u64 %0, t; }" : "=r"(a) : "l"(p));
    return a;
}

#define CP_ASYNC16(dst, src) \
    asm volatile("cp.async.ca.shared.global [%0], [%1], 16;" :: "r"(dst), "l"(src) : "memory")
#define CP_COMMIT()  asm volatile("cp.async.commit_group;" ::: "memory")
#define CP_WAIT1()   asm volatile("cp.async.wait_group 1;" ::: "memory")
#define CP_WAIT0()   asm volatile("cp.async.wait_group 0;" ::: "memory")

__device__ __forceinline__ void mma_f16(float c[4], uint32_t a0, uint32_t a1,
                                        uint32_t a2, uint32_t a3,
                                        uint32_t b0, uint32_t b1) {
    asm volatile(
        "mma.sync.aligned.m16n8k16.row.col.f32.f16.f16.f32 "
        "{%0,%1,%2,%3}, {%4,%5,%6,%7}, {%8,%9}, {%0,%1,%2,%3};"
        : "+f"(c[0]), "+f"(c[1]), "+f"(c[2]), "+f"(c[3])
        : "r"(a0), "r"(a1), "r"(a2), "r"(a3), "r"(b0), "r"(b1));
}
__device__ __forceinline__ void ldsm4(uint32_t r[4], uint32_t addr) {
    asm volatile("ldmatrix.sync.aligned.m8n8.x4.shared.b16 {%0,%1,%2,%3}, [%4];"
                 : "=r"(r[0]), "=r"(r[1]), "=r"(r[2]), "=r"(r[3]) : "r"(addr));
}
__device__ __forceinline__ uint32_t h2u(__half2 h) { return *(uint32_t*)&h; }

// ---------------- transpose kernels (fp16 out) -----------------------------
// #1: Wq/Wk/Wv -> WqkvT + bias concat   (1728 blocks)
__global__ void transpose_wqkv(const float* __restrict__ Wq, const float* __restrict__ Wk,
                               const float* __restrict__ Wv, const float* __restrict__ bq,
                               const float* __restrict__ bk, const float* __restrict__ bv,
                               __half* __restrict__ WqkvT, float* __restrict__ bqkv) {
    __shared__ float t[32][33];
    int idx = blockIdx.x;
    int z = idx / 576, lo = idx % 576;
    const float* src = (z == 0) ? Wq : (z == 1) ? Wk : Wv;
    size_t dstoff = (size_t)z * DD * DD;
    int bx = lo % 24, by = lo / 24;
    int c0 = bx * 32, r0 = by * 32;
    int x = threadIdx.x, y = threadIdx.y;
    #pragma unroll
    for (int i = 0; i < 32; i += 8)
        t[y + i][x] = src[(size_t)(r0 + y + i) * DD + c0 + x];
    __syncthreads();
    #pragma unroll
    for (int i = 0; i < 32; i += 8)
        WqkvT[dstoff + (size_t)(c0 + y + i) * DD + r0 + x] = __float2half(t[x][y + i]);
    if (idx == 0) {
        int tid = y * 32 + x;
        for (int i = tid; i < QKVS; i += 256)
            bqkv[i] = (i < 768) ? bq[i] : (i < 1536) ? bk[i - 768] : bv[i - 1536];
    }
}

// #2: Wo, W1, W2  (576 + 2304 + 2304 = 5184 blocks)
__global__ void transpose_wrest(const float* __restrict__ Wo, const float* __restrict__ W1,
                                const float* __restrict__ W2,
                                __half* __restrict__ WoT, __half* __restrict__ W1T,
                                __half* __restrict__ W2T) {
    __shared__ float t[32][33];
    int idx = blockIdx.x;
    const float* src; __half* dst; int R, C, bx, by;
    if (idx < 576) {
        src = Wo; dst = WoT; R = DD; C = DD; bx = idx % 24; by = idx / 24;
    } else if (idx < 2880) {
        int lo = idx - 576; src = W1; dst = W1T; R = DD; C = FF_; bx = lo % 96; by = lo / 96;
    } else {
        int lo = idx - 2880; src = W2; dst = W2T; R = FF_; C = DD; bx = lo % 24; by = lo / 24;
    }
    int c0 = bx * 32, r0 = by * 32;
    int x = threadIdx.x, y = threadIdx.y;
    #pragma unroll
    for (int i = 0; i < 32; i += 8)
        t[y + i][x] = src[(size_t)(r0 + y + i) * C + c0 + x];
    __syncthreads();
    #pragma unroll
    for (int i = 0; i < 32; i += 8)
        dst[(size_t)(c0 + y + i) * R + r0 + x] = __float2half(t[x][y + i]);
}

// ---------------- LayerNorm (fp16 output) ----------------
__global__ void ln_kernel(const float* __restrict__ x, const float* __restrict__ g,
                          const float* __restrict__ b, __half* __restrict__ y, float eps) {
    int row = blockIdx.x;
    const float* xr = x + (size_t)row * DD;
    __shared__ float red[256];
    int tid = threadIdx.x;

    float s = 0.f;
    for (int d = tid; d < DD; d += 256) s += xr[d];
    red[tid] = s; __syncthreads();
    #pragma unroll
    for (int o = 128; o > 0; o >>= 1) { if (tid < o) red[tid] += red[tid + o]; __syncthreads(); }
    float mu = red[0] * (1.f / DD);
    __syncthreads();

    float v = 0.f;
    for (int d = tid; d < DD; d += 256) { float t = xr[d] - mu; v += t * t; }
    red[tid] = v; __syncthreads();
    #pragma unroll
    for (int o = 128; o > 0; o >>= 1) { if (tid < o) red[tid] += red[tid + o]; __syncthreads(); }
    float inv = rsqrtf(red[0] * (1.f / DD) + eps);

    __half* yr = y + (size_t)row * DD;
    for (int d = tid; d < DD; d += 256)
        yr[d] = __float2half((xr[d] - mu) * inv * g[d] + b[d]);
}

// ====== fp16 mma GEMM with ldmatrix ========================================
// C[M,N] = A[M,K] @ Bt[N,K]^T + epi.  128x128 CTA tile, 8 warps (32x64),
// 3-stage cp.async, K-chunk 64 halves (128B rows, xor swizzle seg^(row&7)).
// EPI: 0 = bias; 1 = bias + residual; 2 = bias + exact GELU
// HALFOUT: 1 -> C is __half, else float
// VTOUT: 1 -> columns [1536,2304) are written TRANSPOSED into Vtp instead of C
#define NSTAGE 3
#define GSMEM (NSTAGE * 32768)   // 96KB

template<int EPI, int HALFOUT, int VTOUT>
__global__ __launch_bounds__(256, 2) void mma_gemm(
    const __half* __restrict__ A, const __half* __restrict__ Bt,
    const float* __restrict__ bias, const float* __restrict__ res,
    void* __restrict__ Cv, __half* __restrict__ Vtp, int K, int N) {
    uint32_t smem_base = smem_u32(smem_raw);

    int tid = threadIdx.x;
    int wid = tid >> 5, lane = tid & 31;
    int r = lane >> 2, l = lane & 3;
    int quad = lane >> 3, qr = lane & 7;
    int row0 = blockIdx.y * 128, col0 = blockIdx.x * 128;
    int m0 = (wid & 3) * 32, n0 = (wid >> 2) * 64;

    // loader mapping
    int m_l = tid >> 3, s_l = tid & 7;
    const __half* srcA = A + (size_t)(row0 + m_l) * K + s_l * 8;
    const __half* srcB = Bt + (size_t)(col0 + m_l) * K + s_l * 8;
    uint32_t dA0 = smem_base + m_l * 128 + ((s_l ^ (m_l & 7)) << 4);
    uint32_t dB0 = dA0 + 16384;

    // ldmatrix addresses
    int rowA = m0 + ((quad & 1) << 3) + qr;
    int xA = rowA & 7, qhA = quad >> 1;
    uint32_t baseA = smem_base + rowA * 128;
    int rowB = n0 + ((quad >> 1) << 3) + qr;
    int xB = rowB & 7, qhB = quad & 1;
    uint32_t baseB = smem_base + 16384 + rowB * 128;

    int nc = K >> 6;

    float acc[2][8][4];
    #pragma unroll
    for (int i = 0; i < 2; i++)
        #pragma unroll
        for (int j = 0; j < 8; j++)
            #pragma unroll
            for (int k = 0; k < 4; k++) acc[i][j][k] = 0.f;

    #pragma unroll
    for (int s = 0; s < NSTAGE - 1; s++) {
        uint32_t so = s * 32768;
        #pragma unroll
        for (int u = 0; u < 4; u++) {
            CP_ASYNC16(dA0 + so + u * 4096, srcA + (size_t)(s * 64) + (size_t)u * 32 * K);
            CP_ASYNC16(dB0 + so + u * 4096, srcB + (size_t)(s * 64) + (size_t)u * 32 * K);
        }
        CP_COMMIT();
    }

    for (int c = 0; c < nc; c++) {
        CP_WAIT1();
        __syncthreads();
        int nstg = c + NSTAGE - 1;
        if (nstg < nc) {
            uint32_t so = (nstg % NSTAGE) * 32768;
            #pragma unroll
            for (int u = 0; u < 4; u++) {
                CP_ASYNC16(dA0 + so + u * 4096, srcA + (size_t)(nstg * 64) + (size_t)u * 32 * K);
                CP_ASYNC16(dB0 + so + u * 4096, srcB + (size_t)(nstg * 64) + (size_t)u * 32 * K);
            }
        }
        CP_COMMIT();

        uint32_t so = (c % NSTAGE) * 32768;
        #pragma unroll
        for (int ks = 0; ks < 4; ks++) {
            uint32_t a0[4], a1[4];
            ldsm4(a0, baseA + so + (((2 * ks + qhA) ^ xA) << 4));
            ldsm4(a1, baseA + so + 2048 + (((2 * ks + qhA) ^ xA) << 4));
            #pragma unroll
            for (int p = 0; p < 4; p++) {
                uint32_t br[4];
                ldsm4(br, baseB + so + p * 2048 + (((2 * ks + qhB) ^ xB) << 4));
                mma_f16(acc[0][2 * p + 0], a0[0], a0[1], a0[2], a0[3], br[0], br[1]);
                mma_f16(acc[0][2 * p + 1], a0[0], a0[1], a0[2], a0[3], br[2], br[3]);
                mma_f16(acc[1][2 * p + 0], a1[0], a1[1], a1[2], a1[3], br[0], br[1]);
                mma_f16(acc[1][2 * p + 1], a1[0], a1[1], a1[2], a1[3], br[2], br[3]);
            }
        }
    }

    // epilogue
    bool vtile = VTOUT && (col0 >= 1536);
    #pragma unroll
    for (int mi = 0; mi < 2; mi++) {
        int rr = row0 + m0 + 16 * mi + r;
        #pragma unroll
        for (int nj = 0; nj < 8; nj++) {
            int cc = col0 + n0 + 8 * nj + 2 * l;
            float b0 = bias[cc], b1 = bias[cc + 1];
            float v0 = acc[mi][nj][0] + b0;
            float v1 = acc[mi][nj][1] + b1;
            float v2 = acc[mi][nj][2] + b0;
            float v3 = acc[mi][nj][3] + b1;
            if (EPI == 1) {
                const float* rp0 = res + (size_t)rr * N + cc;
                const float* rp1 = res + (size_t)(rr + 8) * N + cc;
                v0 += rp0[0]; v1 += rp0[1];
                v2 += rp1[0]; v3 += rp1[1];
            }
            if (EPI == 2) {
                v0 = 0.5f * v0 * (1.f + erff(v0 * 0.70710678118654752f));
                v1 = 0.5f * v1 * (1.f + erff(v1 * 0.70710678118654752f));
                v2 = 0.5f * v2 * (1.f + erff(v2 * 0.70710678118654752f));
                v3 = 0.5f * v3 * (1.f + erff(v3 * 0.70710678118654752f));
            }
            if (VTOUT) {
                if (vtile) {
                    // V columns: write transposed Vt[b][h][d][j]
                    int d = cc - 1536;
                    int hh = d >> 6, dl = d & 63;
                    int b = rr >> 10, j = rr & 1023;
                    __half* vp = Vtp + ((size_t)(b * HH + hh) * 64 + dl) * LL + j;
                    vp[0] = __float2half(v0);
                    vp[LL] = __float2half(v1);
                    vp[8] = __float2half(v2);
                    vp[LL + 8] = __float2half(v3);
                    continue;
                }
            }
            if (HALFOUT) {
                __half* Ch = (__half*)Cv;
                *(__half2*)(Ch + (size_t)rr * N + cc) = __floats2half2_rn(v0, v1);
                *(__half2*)(Ch + (size_t)(rr + 8) * N + cc) = __floats2half2_rn(v2, v3);
            } else {
                float* Cf = (float*)Cv;
                float2 o01 = { v0, v1 };
                float2 o23 = { v2, v3 };
                *(float2*)(Cf + (size_t)rr * N + cc) = o01;
                *(float2*)(Cf + (size_t)(rr + 8) * N + cc) = o23;
            }
        }
    }
}

// ================= fp16 tensor-core flash attention ========================
#define ATB_QS 0         // [128 rows][64 halves]  (128B rows, swizzled)
#define ATB_KS 16384     // [64 j][64 d halves]
#define ATB_VT 24576     // [64 d][64 j halves]
#define ATB_PS 32768     // [128 m][64 j halves]
#define ATB_TB 49152     // float tables
#define TB_REL  0
#define TB_PT   513
#define TB_LEX  1537
#define TB_MROW 1601
#define TB_LROW 1729
#define TB_PIDQ 1857
#define TB_PIDK 1985
#define ATTN_SMEM 57600

__global__ __launch_bounds__(256, 2) void attn_mma(
    const __half* __restrict__ QKV, const __half* __restrict__ Vt,
    const float* __restrict__ rel_emb, const float* __restrict__ ptab,
    const int* __restrict__ pids, const float* __restrict__ lex,
    __half* __restrict__ ctx) {
    char* sb = smem_raw;
    float* tb = (float*)(sb + ATB_TB);
    int* tbi = (int*)tb;
    uint32_t sbase = smem_u32(sb);
    const float LOG2E = 1.44269504089f;

    int tid = threadIdx.x;
    int w = tid >> 5, lane = tid & 31;
    int r = lane >> 2, l = lane & 3;
    int quad = lane >> 3, qr = lane & 7;
    int h = blockIdx.y, bbx = blockIdx.z;
    int i0 = blockIdx.x * 128;

    for (int i = tid; i < 513; i += 256) tb[TB_REL + i] = rel_emb[i * HH + h];
    for (int i = tid; i < 1024; i += 256) tb[TB_PT + i] = ptab[i * HH + h];
    if (tid < 128) {
        tbi[TB_PIDQ + tid] = pids[bbx * LL + i0 + tid];
        tb[TB_MROW + tid] = -1e30f;
        tb[TB_LROW + tid] = 0.f;
    }
    // Q tile: load fp16, scale by 1/8 (exact), store swizzled
    {
        __half2 sc = __float2half2_rn(0.125f);
        #pragma unroll
        for (int u = 0; u < 4; u++) {
            int idx = u * 256 + tid;
            int row = idx >> 3, seg = idx & 7;
            const __half2* src = (const __half2*)(QKV + (size_t)(bbx * LL + i0 + row) * QKVS + h * 64 + seg * 8);
            __half2 v0 = __hmul2(src[0], sc), v1 = __hmul2(src[1], sc);
            __half2 v2 = __hmul2(src[2], sc), v3 = __hmul2(src[3], sc);
            uint4 pk = { h2u(v0), h2u(v1), h2u(v2), h2u(v3) };
            *(uint4*)(sb + ATB_QS + row * 128 + ((seg ^ (row & 7)) << 4)) = pk;
        }
    }
    __syncthreads();

    // Q A-frags resident
    uint32_t aq[4][4];
    {
        int rowA = w * 16 + ((quad & 1) << 3) + qr;
        int xA = rowA & 7, qh = quad >> 1;
        uint32_t baseA = sbase + ATB_QS + rowA * 128;
        #pragma unroll
        for (int ks = 0; ks < 4; ks++)
            ldsm4(aq[ks], baseA + (((2 * ks + qh) ^ xA) << 4));
    }
    int pq0 = tbi[TB_PIDQ + w * 16 + r] * PP;
    int pq1 = tbi[TB_PIDQ + w * 16 + r + 8] * PP;

    float o[8][4];
    #pragma unroll
    for (int nj = 0; nj < 8; nj++)
        #pragma unroll
        for (int k = 0; k < 4; k++) o[nj][k] = 0.f;

    int rowK = ((quad >> 1) << 3) + qr;
    int xK = rowK & 7, qhK = quad & 1;
    uint32_t baseK = sbase + ATB_KS + rowK * 128;
    int rowP = w * 16 + ((quad & 1) << 3) + qr;
    int xP = rowP & 7, qhP = quad >> 1;
    uint32_t baseP = sbase + ATB_PS + rowP * 128;
    uint32_t baseV = sbase + ATB_VT + rowK * 128;

    for (int t = 0; t < 16; t++) {
        int j0 = t * 64;
        #pragma unroll
        for (int u = 0; u < 2; u++) {
            int idx = u * 256 + tid;
            int row = idx >> 3, seg = idx & 7;
            uint32_t sw = ((seg ^ (row & 7)) << 4);
            CP_ASYNC16(sbase + ATB_KS + row * 128 + sw,
                       QKV + (size_t)(bbx * LL + j0 + row) * QKVS + 768 + h * 64 + seg * 8);
            CP_ASYNC16(sbase + ATB_VT + row * 128 + sw,
                       Vt + ((size_t)(bbx * HH + h) * 64 + row) * LL + j0 + seg * 8);
        }
        CP_COMMIT();
        if (tid < 64) {
            tbi[TB_PIDK + tid] = pids[bbx * LL + j0 + tid];
            tb[TB_LEX + tid] = lex[bbx * LL + j0 + tid];
        }
        CP_WAIT0();
        __syncthreads();

        // S = Q @ K^T
        float s[8][4];
        #pragma unroll
        for (int nj = 0; nj < 8; nj++)
            #pragma unroll
            for (int k = 0; k < 4; k++) s[nj][k] = 0.f;
        #pragma unroll
        for (int ks = 0; ks < 4; ks++) {
            #pragma unroll
            for (int p = 0; p < 4; p++) {
                uint32_t br[4];
                ldsm4(br, baseK + p * 2048 + (((2 * ks + qhK) ^ xK) << 4));
                mma_f16(s[2 * p + 0], aq[ks][0], aq[ks][1], aq[ks][2], aq[ks][3], br[0], br[1]);
                mma_f16(s[2 * p + 1], aq[ks][0], aq[ks][1], aq[ks][2], aq[ks][3], br[2], br[3]);
            }
        }

        // biases + row max
        int rg0 = i0 + w * 16 + r, rg1 = rg0 + 8;
        float mx0 = -1e30f, mx1 = -1e30f;
        #pragma unroll
        for (int nj = 0; nj < 8; nj++) {
            int ca = nj * 8 + 2 * l;
            int jga = j0 + ca;
            int pka = tbi[TB_PIDK + ca], pkb = tbi[TB_PIDK + ca + 1];
            float lxa = tb[TB_LEX + ca], lxb = tb[TB_LEX + ca + 1];
            int ra0 = min(max(jga - rg0, -MAXD_), MAXD_) + MAXD_;
            int rb0 = min(max(jga + 1 - rg0, -MAXD_), MAXD_) + MAXD_;
            int ra1 = min(max(jga - rg1, -MAXD_), MAXD_) + MAXD_;
            int rb1 = min(max(jga + 1 - rg1, -MAXD_), MAXD_) + MAXD_;
            s[nj][0] += tb[TB_REL + ra0] + tb[TB_PT + pq0 + pka] + lxa;
            s[nj][1] += tb[TB_REL + rb0] + tb[TB_PT + pq0 + pkb] + lxb;
            s[nj][2] += tb[TB_REL + ra1] + tb[TB_PT + pq1 + pka] + lxa;
            s[nj][3] += tb[TB_REL + rb1] + tb[TB_PT + pq1 + pkb] + lxb;
            mx0 = fmaxf(mx0, fmaxf(s[nj][0], s[nj][1]));
            mx1 = fmaxf(mx1, fmaxf(s[nj][2], s[nj][3]));
        }
        mx0 = fmaxf(mx0, __shfl_xor_sync(0xffffffffu, mx0, 1));
        mx0 = fmaxf(mx0, __shfl_xor_sync(0xffffffffu, mx0, 2));
        mx1 = fmaxf(mx1, __shfl_xor_sync(0xffffffffu, mx1, 1));
        mx1 = fmaxf(mx1, __shfl_xor_sync(0xffffffffu, mx1, 2));

        float mo0 = tb[TB_MROW + w * 16 + r], mo1 = tb[TB_MROW + w * 16 + r + 8];
        float mn0 = fmaxf(mo0, mx0), mn1 = fmaxf(mo1, mx1);
        float al0 = exp2f((mo0 - mn0) * LOG2E), al1 = exp2f((mo1 - mn1) * LOG2E);
        float sum0 = 0.f, sum1 = 0.f;
        int m0r = w * 16 + r;
        #pragma unroll
        for (int nj = 0; nj < 8; nj++) {
            float p0 = exp2f((s[nj][0] - mn0) * LOG2E);
            float p1 = exp2f((s[nj][1] - mn0) * LOG2E);
            float p2 = exp2f((s[nj][2] - mn1) * LOG2E);
            float p3 = exp2f((s[nj][3] - mn1) * LOG2E);
            sum0 += p0 + p1; sum1 += p2 + p3;
            *(__half2*)(sb + ATB_PS + m0r * 128 + ((nj ^ (m0r & 7)) << 4) + 4 * l)
                = __floats2half2_rn(p0, p1);
            *(__half2*)(sb + ATB_PS + (m0r + 8) * 128 + ((nj ^ ((m0r + 8) & 7)) << 4) + 4 * l)
                = __floats2half2_rn(p2, p3);
            o[nj][0] *= al0; o[nj][1] *= al0; o[nj][2] *= al1; o[nj][3] *= al1;
        }
        sum0 += __shfl_xor_sync(0xffffffffu, sum0, 1);
        sum0 += __shfl_xor_sync(0xffffffffu, sum0, 2);
        sum1 += __shfl_xor_sync(0xffffffffu, sum1, 1);
        sum1 += __shfl_xor_sync(0xffffffffu, sum1, 2);
        if (l == 0) {
            tb[TB_MROW + m0r] = mn0;
            tb[TB_MROW + m0r + 8] = mn1;
            tb[TB_LROW + m0r] = tb[TB_LROW + m0r] * al0 + sum0;
            tb[TB_LROW + m0r + 8] = tb[TB_LROW + m0r + 8] * al1 + sum1;
        }
        __syncwarp();

        // O += P @ V
        #pragma unroll
        for (int ks = 0; ks < 4; ks++) {
            uint32_t ap[4];
            ldsm4(ap, baseP + (((2 * ks + qhP) ^ xP) << 4));
            #pragma unroll
            for (int p = 0; p < 4; p++) {
                uint32_t bv[4];
                ldsm4(bv, baseV + p * 2048 + (((2 * ks + qhK) ^ xK) << 4));
                mma_f16(o[2 * p + 0], ap[0], ap[1], ap[2], ap[3], bv[0], bv[1]);
                mma_f16(o[2 * p + 1], ap[0], ap[1], ap[2], ap[3], bv[2], bv[3]);
            }
        }
        __syncthreads();
    }

    // finalize
    float inv0 = 1.f / tb[TB_LROW + w * 16 + r];
    float inv1 = 1.f / tb[TB_LROW + w * 16 + r + 8];
    int row0g = bbx * LL + i0 + w * 16 + r;
    #pragma unroll
    for (int nj = 0; nj < 8; nj++) {
        *(__half2*)(ctx + (size_t)row0g * DD + h * 64 + nj * 8 + 2 * l)
            = __floats2half2_rn(o[nj][0] * inv0, o[nj][1] * inv0);
        *(__half2*)(ctx + (size_t)(row0g + 8) * DD + h * 64 + nj * 8 + 2 * l)
            = __floats2half2_rn(o[nj][2] * inv1, o[nj][3] * inv1);
    }
}

// ---------------- launch ----------------
extern "C" void kernel_launch(void* const* d_in, const int* in_sizes, int n_in,
                              void* d_out, int out_size) {
    const float* x      = (const float*)d_in[0];
    const int*   postag = (const int*)  d_in[1];
    const float* lexm   = (const float*)d_in[2];
    const float* ln1g   = (const float*)d_in[3];
    const float* ln1b   = (const float*)d_in[4];
    const float* Wq     = (const float*)d_in[5];
    const float* bq     = (const float*)d_in[6];
    const float* Wk     = (const float*)d_in[7];
    const float* bk     = (const float*)d_in[8];
    const float* Wv     = (const float*)d_in[9];
    const float* bv     = (const float*)d_in[10];
    const float* Wo     = (const float*)d_in[11];
    const float* bo     = (const float*)d_in[12];
    const float* rel    = (const float*)d_in[13];
    const float* ptab   = (const float*)d_in[14];
    const float* ln2g   = (const float*)d_in[15];
    const float* ln2b   = (const float*)d_in[16];
    const float* W1     = (const float*)d_in[17];
    const float* b1     = (const float*)d_in[18];
    const float* W2     = (const float*)d_in[19];
    const float* b2     = (const float*)d_in[20];
    float* out = (float*)d_out;

    __half *qin, *QKVb, *Vt, *ctx, *h2, *ff;
    __half *WqkvT, *WoT, *W1T, *W2T;
    float *res1, *bqkv;
    cudaGetSymbolAddress((void**)&qin,   g_qin);
    cudaGetSymbolAddress((void**)&QKVb,  g_QKV);
    cudaGetSymbolAddress((void**)&Vt,    g_Vt);
    cudaGetSymbolAddress((void**)&ctx,   g_ctx);
    cudaGetSymbolAddress((void**)&res1,  g_res1);
    cudaGetSymbolAddress((void**)&h2,    g_h2);
    cudaGetSymbolAddress((void**)&ff,    g_ff);
    cudaGetSymbolAddress((void**)&WqkvT, g_WqkvT);
    cudaGetSymbolAddress((void**)&bqkv,  g_bqkv);
    cudaGetSymbolAddress((void**)&WoT,   g_WoT);
    cudaGetSymbolAddress((void**)&W1T,   g_W1T);
    cudaGetSymbolAddress((void**)&W2T,   g_W2T);

    cudaFuncSetAttribute(attn_mma, cudaFuncAttributeMaxDynamicSharedMemorySize, ATTN_SMEM);
    cudaFuncSetAttribute(mma_gemm<0,1,1>, cudaFuncAttributeMaxDynamicSharedMemorySize, GSMEM);
    cudaFuncSetAttribute(mma_gemm<1,0,0>, cudaFuncAttributeMaxDynamicSharedMemorySize, GSMEM);
    cudaFuncSetAttribute(mma_gemm<2,1,0>, cudaFuncAttributeMaxDynamicSharedMemorySize, GSMEM);

    // 0: QKV weight transpose
    transpose_wqkv<<<1728, dim3(32, 8)>>>(Wq, Wk, Wv, bq, bk, bv, WqkvT, bqkv);
    // 1: other weight transposes
    transpose_wrest<<<5184, dim3(32, 8)>>>(Wo, W1, W2, WoT, W1T, W2T);
    // 2: LN1 -> fp16
    ln_kernel<<<ML, 256>>>(x, ln1g, ln1b, qin, 1e-6f);
    // 3: fused QKV projection (fp16 out; V part written transposed to Vt)  <- ncu capture
    mma_gemm<0,1,1><<<dim3(QKVS / 128, ML / 128), 256, GSMEM>>>(qin, WqkvT, bqkv, nullptr, QKVb, Vt, DD, QKVS);
    // 4: fp16 tensor-core attention
    attn_mma<<<dim3(LL / 128, HH, BB), 256, ATTN_SMEM>>>(QKVb, Vt, rel, ptab, postag, lexm, ctx);
    // 5: output projection + residual (fp32 out)
    mma_gemm<1,0,0><<<dim3(DD / 128, ML / 128), 256, GSMEM>>>(ctx, WoT, bo, x, res1, nullptr, DD, DD);
    // 6: LN2 -> fp16
    ln_kernel<<<ML, 256>>>(res1, ln2g, ln2b, h2, 1e-5f);
    // 7: FFN up + GELU (fp16 out)
    mma_gemm<2,1,0><<<dim3(FF_ / 128, ML / 128), 256, GSMEM>>>(h2, W1T, b1, nullptr, ff, nullptr, DD, FF_);
    // 8: FFN down + bias + residual -> out (fp32)
    mma_gemm<1,0,0><<<dim3(DD / 128, ML / 128), 256, GSMEM>>>(ff, W2T, b2, res1, out, nullptr, FF_, DD);
}

// round 12
// speedup vs baseline: 1.0650x; 1.0650x over previous
#include <cuda_runtime.h>
#include <cuda_fp16.h>
#include <math.h>
#include <stdint.h>

// Problem constants
#define BB   4
#define LL   1024
#define DD   768
#define HH   12
#define FF_  3072
#define PP   32
#define MAXD_ 256
#define ML   (BB*LL)   // 4096 rows
#define QKVS 2304      // fused QKV row stride

// ---------------- scratch (device globals; no runtime allocation) ----------
__device__ __half g_qin[ML*DD];
__device__ __half g_QKV[ML*QKVS];
__device__ __half g_Vt[(size_t)BB*HH*64*LL];   // [b][h][d][j]
__device__ __half g_ctx[ML*DD];
__device__ float  g_res1[ML*DD];
__device__ __half g_h2[ML*DD];
__device__ __half g_ff[ML*FF_];
// transposed weights [N,K] fp16
__device__ __half g_WqkvT[QKVS*DD];
__device__ float  g_bqkv[QKVS];
__device__ __half g_WoT[DD*DD];
__device__ __half g_W1T[FF_*DD];
__device__ __half g_W2T[DD*FF_];

// single extern shared symbol for all kernels
extern __shared__ char smem_raw[];

// ======================= helpers =====================
__device__ __forceinline__ uint32_t smem_u32(const void* p) {
    uint32_t a;
    asm("{ .reg .u64 t; cvta.to.shared.u64 t, %1; cvt.u32.u64 %0, t; }" : "=r"(a) : "l"(p));
    return a;
}

#define CP_ASYNC16(dst, src) \
    asm volatile("cp.async.ca.shared.global [%0], [%1], 16;" :: "r"(dst), "l"(src) : "memory")
#define CP_COMMIT()  asm volatile("cp.async.commit_group;" ::: "memory")
#define CP_WAIT1()   asm volatile("cp.async.wait_group 1;" ::: "memory")
#define CP_WAIT0()   asm volatile("cp.async.wait_group 0;" ::: "memory")

__device__ __forceinline__ void mma_f16(float c[4], uint32_t a0, uint32_t a1,
                                        uint32_t a2, uint32_t a3,
                                        uint32_t b0, uint32_t b1) {
    asm volatile(
        "mma.sync.aligned.m16n8k16.row.col.f32.f16.f16.f32 "
        "{%0,%1,%2,%3}, {%4,%5,%6,%7}, {%8,%9}, {%0,%1,%2,%3};"
        : "+f"(c[0]), "+f"(c[1]), "+f"(c[2]), "+f"(c[3])
        : "r"(a0), "r"(a1), "r"(a2), "r"(a3), "r"(b0), "r"(b1));
}
__device__ __forceinline__ void ldsm4(uint32_t r[4], uint32_t addr) {
    asm volatile("ldmatrix.sync.aligned.m8n8.x4.shared.b16 {%0,%1,%2,%3}, [%4];"
                 : "=r"(r[0]), "=r"(r[1]), "=r"(r[2]), "=r"(r[3]) : "r"(addr));
}
__device__ __forceinline__ uint32_t h2u(__half2 h) { return *(uint32_t*)&h; }

// ---------------- transpose kernels (fp16 out) -----------------------------
__global__ void transpose_wqkv(const float* __restrict__ Wq, const float* __restrict__ Wk,
                               const float* __restrict__ Wv, const float* __restrict__ bq,
                               const float* __restrict__ bk, const float* __restrict__ bv,
                               __half* __restrict__ WqkvT, float* __restrict__ bqkv) {
    __shared__ float t[32][33];
    int idx = blockIdx.x;
    int z = idx / 576, lo = idx % 576;
    const float* src = (z == 0) ? Wq : (z == 1) ? Wk : Wv;
    size_t dstoff = (size_t)z * DD * DD;
    int bx = lo % 24, by = lo / 24;
    int c0 = bx * 32, r0 = by * 32;
    int x = threadIdx.x, y = threadIdx.y;
    #pragma unroll
    for (int i = 0; i < 32; i += 8)
        t[y + i][x] = src[(size_t)(r0 + y + i) * DD + c0 + x];
    __syncthreads();
    #pragma unroll
    for (int i = 0; i < 32; i += 8)
        WqkvT[dstoff + (size_t)(c0 + y + i) * DD + r0 + x] = __float2half(t[x][y + i]);
    if (idx == 0) {
        int tid = y * 32 + x;
        for (int i = tid; i < QKVS; i += 256)
            bqkv[i] = (i < 768) ? bq[i] : (i < 1536) ? bk[i - 768] : bv[i - 1536];
    }
}

__global__ void transpose_wrest(const float* __restrict__ Wo, const float* __restrict__ W1,
                                const float* __restrict__ W2,
                                __half* __restrict__ WoT, __half* __restrict__ W1T,
                                __half* __restrict__ W2T) {
    __shared__ float t[32][33];
    int idx = blockIdx.x;
    const float* src; __half* dst; int R, C, bx, by;
    if (idx < 576) {
        src = Wo; dst = WoT; R = DD; C = DD; bx = idx % 24; by = idx / 24;
    } else if (idx < 2880) {
        int lo = idx - 576; src = W1; dst = W1T; R = DD; C = FF_; bx = lo % 96; by = lo / 96;
    } else {
        int lo = idx - 2880; src = W2; dst = W2T; R = FF_; C = DD; bx = lo % 24; by = lo / 24;
    }
    int c0 = bx * 32, r0 = by * 32;
    int x = threadIdx.x, y = threadIdx.y;
    #pragma unroll
    for (int i = 0; i < 32; i += 8)
        t[y + i][x] = src[(size_t)(r0 + y + i) * C + c0 + x];
    __syncthreads();
    #pragma unroll
    for (int i = 0; i < 32; i += 8)
        dst[(size_t)(c0 + y + i) * R + r0 + x] = __float2half(t[x][y + i]);
}

// ---------------- LayerNorm (fp16 output) ----------------
__global__ void ln_kernel(const float* __restrict__ x, const float* __restrict__ g,
                          const float* __restrict__ b, __half* __restrict__ y, float eps) {
    int row = blockIdx.x;
    const float* xr = x + (size_t)row * DD;
    __shared__ float red[256];
    int tid = threadIdx.x;

    float s = 0.f;
    for (int d = tid; d < DD; d += 256) s += xr[d];
    red[tid] = s; __syncthreads();
    #pragma unroll
    for (int o = 128; o > 0; o >>= 1) { if (tid < o) red[tid] += red[tid + o]; __syncthreads(); }
    float mu = red[0] * (1.f / DD);
    __syncthreads();

    float v = 0.f;
    for (int d = tid; d < DD; d += 256) { float t = xr[d] - mu; v += t * t; }
    red[tid] = v; __syncthreads();
    #pragma unroll
    for (int o = 128; o > 0; o >>= 1) { if (tid < o) red[tid] += red[tid + o]; __syncthreads(); }
    float inv = rsqrtf(red[0] * (1.f / DD) + eps);

    __half* yr = y + (size_t)row * DD;
    for (int d = tid; d < DD; d += 256)
        yr[d] = __float2half((xr[d] - mu) * inv * g[d] + b[d]);
}

// ====== fp16 mma GEMM, 64x64 warp tiles ====================================
// C[M,N] = A[M,K] @ Bt[N,K]^T + epi.  128x128 CTA tile, 4 warps (64x64 each),
// 3-stage cp.async, K-chunk 64 halves (128B rows, xor swizzle seg^(row&7)).
// EPI: 0 = bias; 1 = bias + residual; 2 = bias + exact GELU
// HALFOUT: 1 -> C is __half, else float
// VTOUT: 1 -> columns [1536,2304) are written TRANSPOSED into Vtp instead of C
#define NSTAGE 3
#define GSMEM (NSTAGE * 32768)   // 96KB

template<int EPI, int HALFOUT, int VTOUT>
__global__ __launch_bounds__(128, 2) void mma_gemm(
    const __half* __restrict__ A, const __half* __restrict__ Bt,
    const float* __restrict__ bias, const float* __restrict__ res,
    void* __restrict__ Cv, __half* __restrict__ Vtp, int K, int N) {
    uint32_t smem_base = smem_u32(smem_raw);

    int tid = threadIdx.x;
    int wid = tid >> 5, lane = tid & 31;
    int r = lane >> 2, l = lane & 3;
    int quad = lane >> 3, qr = lane & 7;
    int row0 = blockIdx.y * 128, col0 = blockIdx.x * 128;
    int m0 = (wid & 1) * 64, n0 = (wid >> 1) * 64;

    // loader mapping: 128 threads cover 16 rows x 8 segs per u-step (8 steps)
    int m_l = tid >> 3, s_l = tid & 7;   // m_l 0..15
    const __half* srcA = A + (size_t)(row0 + m_l) * K + s_l * 8;
    const __half* srcB = Bt + (size_t)(col0 + m_l) * K + s_l * 8;
    uint32_t dA0 = smem_base + m_l * 128 + ((s_l ^ (m_l & 7)) << 4);
    uint32_t dB0 = dA0 + 16384;

    // ldmatrix per-thread addresses
    // A frag (mi): rows m0 + 16*mi + (quad&1)*8 + qr
    int arow = m0 + ((quad & 1) << 3) + qr;
    int xA = arow & 7, qhA = quad >> 1;
    uint32_t baseA = smem_base + arow * 128;
    // B frag (p): rows n0 + 16*p + (quad>>1)*8 + qr
    int brow = n0 + ((quad >> 1) << 3) + qr;
    int xB = brow & 7, qhB = quad & 1;
    uint32_t baseB = smem_base + 16384 + brow * 128;

    int nc = K >> 6;

    float acc[4][8][4];
    #pragma unroll
    for (int i = 0; i < 4; i++)
        #pragma unroll
        for (int j = 0; j < 8; j++)
            #pragma unroll
            for (int k = 0; k < 4; k++) acc[i][j][k] = 0.f;

    #pragma unroll
    for (int s = 0; s < NSTAGE - 1; s++) {
        uint32_t so = s * 32768;
        #pragma unroll
        for (int u = 0; u < 8; u++) {
            CP_ASYNC16(dA0 + so + u * 2048, srcA + (size_t)(s * 64) + (size_t)u * 16 * K);
            CP_ASYNC16(dB0 + so + u * 2048, srcB + (size_t)(s * 64) + (size_t)u * 16 * K);
        }
        CP_COMMIT();
    }

    for (int c = 0; c < nc; c++) {
        CP_WAIT1();
        __syncthreads();
        int nstg = c + NSTAGE - 1;
        if (nstg < nc) {
            uint32_t so = (nstg % NSTAGE) * 32768;
            #pragma unroll
            for (int u = 0; u < 8; u++) {
                CP_ASYNC16(dA0 + so + u * 2048, srcA + (size_t)(nstg * 64) + (size_t)u * 16 * K);
                CP_ASYNC16(dB0 + so + u * 2048, srcB + (size_t)(nstg * 64) + (size_t)u * 16 * K);
            }
        }
        CP_COMMIT();

        uint32_t so = (c % NSTAGE) * 32768;
        #pragma unroll
        for (int ks = 0; ks < 4; ks++) {
            uint32_t segA = ((2 * ks + qhA) ^ xA) << 4;
            uint32_t segB = ((2 * ks + qhB) ^ xB) << 4;
            uint32_t a[4][4];
            #pragma unroll
            for (int mi = 0; mi < 4; mi++)
                ldsm4(a[mi], baseA + so + mi * 2048 + segA);
            #pragma unroll
            for (int p = 0; p < 4; p++) {
                uint32_t br[4];
                ldsm4(br, baseB + so + p * 2048 + segB);
                #pragma unroll
                for (int mi = 0; mi < 4; mi++) {
                    mma_f16(acc[mi][2 * p + 0], a[mi][0], a[mi][1], a[mi][2], a[mi][3], br[0], br[1]);
                    mma_f16(acc[mi][2 * p + 1], a[mi][0], a[mi][1], a[mi][2], a[mi][3], br[2], br[3]);
                }
            }
        }
    }

    // epilogue
    bool vtile = VTOUT && (col0 >= 1536);
    #pragma unroll
    for (int mi = 0; mi < 4; mi++) {
        int rr = row0 + m0 + 16 * mi + r;
        #pragma unroll
        for (int nj = 0; nj < 8; nj++) {
            int cc = col0 + n0 + 8 * nj + 2 * l;
            float b0 = bias[cc], b1 = bias[cc + 1];
            float v0 = acc[mi][nj][0] + b0;
            float v1 = acc[mi][nj][1] + b1;
            float v2 = acc[mi][nj][2] + b0;
            float v3 = acc[mi][nj][3] + b1;
            if (EPI == 1) {
                const float* rp0 = res + (size_t)rr * N + cc;
                const float* rp1 = res + (size_t)(rr + 8) * N + cc;
                v0 += rp0[0]; v1 += rp0[1];
                v2 += rp1[0]; v3 += rp1[1];
            }
            if (EPI == 2) {
                v0 = 0.5f * v0 * (1.f + erff(v0 * 0.70710678118654752f));
                v1 = 0.5f * v1 * (1.f + erff(v1 * 0.70710678118654752f));
                v2 = 0.5f * v2 * (1.f + erff(v2 * 0.70710678118654752f));
                v3 = 0.5f * v3 * (1.f + erff(v3 * 0.70710678118654752f));
            }
            if (VTOUT) {
                if (vtile) {
                    int d = cc - 1536;
                    int hh = d >> 6, dl = d & 63;
                    int b = rr >> 10, j = rr & 1023;
                    __half* vp = Vtp + ((size_t)(b * HH + hh) * 64 + dl) * LL + j;
                    vp[0] = __float2half(v0);
                    vp[LL] = __float2half(v1);
                    vp[8] = __float2half(v2);
                    vp[LL + 8] = __float2half(v3);
                    continue;
                }
            }
            if (HALFOUT) {
                __half* Ch = (__half*)Cv;
                *(__half2*)(Ch + (size_t)rr * N + cc) = __floats2half2_rn(v0, v1);
                *(__half2*)(Ch + (size_t)(rr + 8) * N + cc) = __floats2half2_rn(v2, v3);
            } else {
                float* Cf = (float*)Cv;
                float2 o01 = { v0, v1 };
                float2 o23 = { v2, v3 };
                *(float2*)(Cf + (size_t)rr * N + cc) = o01;
                *(float2*)(Cf + (size_t)(rr + 8) * N + cc) = o23;
            }
        }
    }
}

// ================= fp16 tensor-core flash attention ========================
#define ATB_QS 0         // [128 rows][64 halves]  (128B rows, swizzled)
#define ATB_KS 16384     // [64 j][64 d halves]
#define ATB_VT 24576     // [64 d][64 j halves]
#define ATB_PS 32768     // [128 m][64 j halves]
#define ATB_TB 49152     // float tables
#define TB_REL  0
#define TB_PT   513
#define TB_LEX  1537
#define TB_MROW 1601
#define TB_LROW 1729
#define TB_PIDQ 1857
#define TB_PIDK 1985
#define ATTN_SMEM 57600

__global__ __launch_bounds__(256, 2) void attn_mma(
    const __half* __restrict__ QKV, const __half* __restrict__ Vt,
    const float* __restrict__ rel_emb, const float* __restrict__ ptab,
    const int* __restrict__ pids, const float* __restrict__ lex,
    __half* __restrict__ ctx) {
    char* sb = smem_raw;
    float* tb = (float*)(sb + ATB_TB);
    int* tbi = (int*)tb;
    uint32_t sbase = smem_u32(sb);
    const float LOG2E = 1.44269504089f;

    int tid = threadIdx.x;
    int w = tid >> 5, lane = tid & 31;
    int r = lane >> 2, l = lane & 3;
    int quad = lane >> 3, qr = lane & 7;
    int h = blockIdx.y, bbx = blockIdx.z;
    int i0 = blockIdx.x * 128;

    for (int i = tid; i < 513; i += 256) tb[TB_REL + i] = rel_emb[i * HH + h];
    for (int i = tid; i < 1024; i += 256) tb[TB_PT + i] = ptab[i * HH + h];
    if (tid < 128) {
        tbi[TB_PIDQ + tid] = pids[bbx * LL + i0 + tid];
        tb[TB_MROW + tid] = -1e30f;
        tb[TB_LROW + tid] = 0.f;
    }
    {
        __half2 sc = __float2half2_rn(0.125f);
        #pragma unroll
        for (int u = 0; u < 4; u++) {
            int idx = u * 256 + tid;
            int row = idx >> 3, seg = idx & 7;
            const __half2* src = (const __half2*)(QKV + (size_t)(bbx * LL + i0 + row) * QKVS + h * 64 + seg * 8);
            __half2 v0 = __hmul2(src[0], sc), v1 = __hmul2(src[1], sc);
            __half2 v2 = __hmul2(src[2], sc), v3 = __hmul2(src[3], sc);
            uint4 pk = { h2u(v0), h2u(v1), h2u(v2), h2u(v3) };
            *(uint4*)(sb + ATB_QS + row * 128 + ((seg ^ (row & 7)) << 4)) = pk;
        }
    }
    __syncthreads();

    uint32_t aq[4][4];
    {
        int rowA = w * 16 + ((quad & 1) << 3) + qr;
        int xA = rowA & 7, qh = quad >> 1;
        uint32_t baseA = sbase + ATB_QS + rowA * 128;
        #pragma unroll
        for (int ks = 0; ks < 4; ks++)
            ldsm4(aq[ks], baseA + (((2 * ks + qh) ^ xA) << 4));
    }
    int pq0 = tbi[TB_PIDQ + w * 16 + r] * PP;
    int pq1 = tbi[TB_PIDQ + w * 16 + r + 8] * PP;

    float o[8][4];
    #pragma unroll
    for (int nj = 0; nj < 8; nj++)
        #pragma unroll
        for (int k = 0; k < 4; k++) o[nj][k] = 0.f;

    int rowK = ((quad >> 1) << 3) + qr;
    int xK = rowK & 7, qhK = quad & 1;
    uint32_t baseK = sbase + ATB_KS + rowK * 128;
    int rowP = w * 16 + ((quad & 1) << 3) + qr;
    int xP = rowP & 7, qhP = quad >> 1;
    uint32_t baseP = sbase + ATB_PS + rowP * 128;
    uint32_t baseV = sbase + ATB_VT + rowK * 128;

    for (int t = 0; t < 16; t++) {
        int j0 = t * 64;
        #pragma unroll
        for (int u = 0; u < 2; u++) {
            int idx = u * 256 + tid;
            int row = idx >> 3, seg = idx & 7;
            uint32_t sw = ((seg ^ (row & 7)) << 4);
            CP_ASYNC16(sbase + ATB_KS + row * 128 + sw,
                       QKV + (size_t)(bbx * LL + j0 + row) * QKVS + 768 + h * 64 + seg * 8);
            CP_ASYNC16(sbase + ATB_VT + row * 128 + sw,
                       Vt + ((size_t)(bbx * HH + h) * 64 + row) * LL + j0 + seg * 8);
        }
        CP_COMMIT();
        if (tid < 64) {
            tbi[TB_PIDK + tid] = pids[bbx * LL + j0 + tid];
            tb[TB_LEX + tid] = lex[bbx * LL + j0 + tid];
        }
        CP_WAIT0();
        __syncthreads();

        // S = Q @ K^T
        float s[8][4];
        #pragma unroll
        for (int nj = 0; nj < 8; nj++)
            #pragma unroll
            for (int k = 0; k < 4; k++) s[nj][k] = 0.f;
        #pragma unroll
        for (int ks = 0; ks < 4; ks++) {
            #pragma unroll
            for (int p = 0; p < 4; p++) {
                uint32_t br[4];
                ldsm4(br, baseK + p * 2048 + (((2 * ks + qhK) ^ xK) << 4));
                mma_f16(s[2 * p + 0], aq[ks][0], aq[ks][1], aq[ks][2], aq[ks][3], br[0], br[1]);
                mma_f16(s[2 * p + 1], aq[ks][0], aq[ks][1], aq[ks][2], aq[ks][3], br[2], br[3]);
            }
        }

        // biases + row max
        int rg0 = i0 + w * 16 + r, rg1 = rg0 + 8;
        float mx0 = -1e30f, mx1 = -1e30f;
        #pragma unroll
        for (int nj = 0; nj < 8; nj++) {
            int ca = nj * 8 + 2 * l;
            int jga = j0 + ca;
            int pka = tbi[TB_PIDK + ca], pkb = tbi[TB_PIDK + ca + 1];
            float lxa = tb[TB_LEX + ca], lxb = tb[TB_LEX + ca + 1];
            int ra0 = min(max(jga - rg0, -MAXD_), MAXD_) + MAXD_;
            int rb0 = min(max(jga + 1 - rg0, -MAXD_), MAXD_) + MAXD_;
            int ra1 = min(max(jga - rg1, -MAXD_), MAXD_) + MAXD_;
            int rb1 = min(max(jga + 1 - rg1, -MAXD_), MAXD_) + MAXD_;
            s[nj][0] += tb[TB_REL + ra0] + tb[TB_PT + pq0 + pka] + lxa;
            s[nj][1] += tb[TB_REL + rb0] + tb[TB_PT + pq0 + pkb] + lxb;
            s[nj][2] += tb[TB_REL + ra1] + tb[TB_PT + pq1 + pka] + lxa;
            s[nj][3] += tb[TB_REL + rb1] + tb[TB_PT + pq1 + pkb] + lxb;
            mx0 = fmaxf(mx0, fmaxf(s[nj][0], s[nj][1]));
            mx1 = fmaxf(mx1, fmaxf(s[nj][2], s[nj][3]));
        }
        mx0 = fmaxf(mx0, __shfl_xor_sync(0xffffffffu, mx0, 1));
        mx0 = fmaxf(mx0, __shfl_xor_sync(0xffffffffu, mx0, 2));
        mx1 = fmaxf(mx1, __shfl_xor_sync(0xffffffffu, mx1, 1));
        mx1 = fmaxf(mx1, __shfl_xor_sync(0xffffffffu, mx1, 2));

        float mo0 = tb[TB_MROW + w * 16 + r], mo1 = tb[TB_MROW + w * 16 + r + 8];
        float mn0 = fmaxf(mo0, mx0), mn1 = fmaxf(mo1, mx1);
        float al0 = exp2f((mo0 - mn0) * LOG2E), al1 = exp2f((mo1 - mn1) * LOG2E);
        float sum0 = 0.f, sum1 = 0.f;
        int m0r = w * 16 + r;
        #pragma unroll
        for (int nj = 0; nj < 8; nj++) {
            float p0 = exp2f((s[nj][0] - mn0) * LOG2E);
            float p1 = exp2f((s[nj][1] - mn0) * LOG2E);
            float p2 = exp2f((s[nj][2] - mn1) * LOG2E);
            float p3 = exp2f((s[nj][3] - mn1) * LOG2E);
            sum0 += p0 + p1; sum1 += p2 + p3;
            *(__half2*)(sb + ATB_PS + m0r * 128 + ((nj ^ (m0r & 7)) << 4) + 4 * l)
                = __floats2half2_rn(p0, p1);
            *(__half2*)(sb + ATB_PS + (m0r + 8) * 128 + ((nj ^ ((m0r + 8) & 7)) << 4) + 4 * l)
                = __floats2half2_rn(p2, p3);
            o[nj][0] *= al0; o[nj][1] *= al0; o[nj][2] *= al1; o[nj][3] *= al1;
        }
        sum0 += __shfl_xor_sync(0xffffffffu, sum0, 1);
        sum0 += __shfl_xor_sync(0xffffffffu, sum0, 2);
        sum1 += __shfl_xor_sync(0xffffffffu, sum1, 1);
        sum1 += __shfl_xor_sync(0xffffffffu, sum1, 2);
        if (l == 0) {
            tb[TB_MROW + m0r] = mn0;
            tb[TB_MROW + m0r + 8] = mn1;
            tb[TB_LROW + m0r] = tb[TB_LROW + m0r] * al0 + sum0;
            tb[TB_LROW + m0r + 8] = tb[TB_LROW + m0r + 8] * al1 + sum1;
        }
        __syncwarp();

        // O += P @ V
        #pragma unroll
        for (int ks = 0; ks < 4; ks++) {
            uint32_t ap[4];
            ldsm4(ap, baseP + (((2 * ks + qhP) ^ xP) << 4));
            #pragma unroll
            for (int p = 0; p < 4; p++) {
                uint32_t bv[4];
                ldsm4(bv, baseV + p * 2048 + (((2 * ks + qhK) ^ xK) << 4));
                mma_f16(o[2 * p + 0], ap[0], ap[1], ap[2], ap[3], bv[0], bv[1]);
                mma_f16(o[2 * p + 1], ap[0], ap[1], ap[2], ap[3], bv[2], bv[3]);
            }
        }
        __syncthreads();
    }

    // finalize
    float inv0 = 1.f / tb[TB_LROW + w * 16 + r];
    float inv1 = 1.f / tb[TB_LROW + w * 16 + r + 8];
    int row0g = bbx * LL + i0 + w * 16 + r;
    #pragma unroll
    for (int nj = 0; nj < 8; nj++) {
        *(__half2*)(ctx + (size_t)row0g * DD + h * 64 + nj * 8 + 2 * l)
            = __floats2half2_rn(o[nj][0] * inv0, o[nj][1] * inv0);
        *(__half2*)(ctx + (size_t)(row0g + 8) * DD + h * 64 + nj * 8 + 2 * l)
            = __floats2half2_rn(o[nj][2] * inv1, o[nj][3] * inv1);
    }
}

// ---------------- launch ----------------
extern "C" void kernel_launch(void* const* d_in, const int* in_sizes, int n_in,
                              void* d_out, int out_size) {
    const float* x      = (const float*)d_in[0];
    const int*   postag = (const int*)  d_in[1];
    const float* lexm   = (const float*)d_in[2];
    const float* ln1g   = (const float*)d_in[3];
    const float* ln1b   = (const float*)d_in[4];
    const float* Wq     = (const float*)d_in[5];
    const float* bq     = (const float*)d_in[6];
    const float* Wk     = (const float*)d_in[7];
    const float* bk     = (const float*)d_in[8];
    const float* Wv     = (const float*)d_in[9];
    const float* bv     = (const float*)d_in[10];
    const float* Wo     = (const float*)d_in[11];
    const float* bo     = (const float*)d_in[12];
    const float* rel    = (const float*)d_in[13];
    const float* ptab   = (const float*)d_in[14];
    const float* ln2g   = (const float*)d_in[15];
    const float* ln2b   = (const float*)d_in[16];
    const float* W1     = (const float*)d_in[17];
    const float* b1     = (const float*)d_in[18];
    const float* W2     = (const float*)d_in[19];
    const float* b2     = (const float*)d_in[20];
    float* out = (float*)d_out;

    __half *qin, *QKVb, *Vt, *ctx, *h2, *ff;
    __half *WqkvT, *WoT, *W1T, *W2T;
    float *res1, *bqkv;
    cudaGetSymbolAddress((void**)&qin,   g_qin);
    cudaGetSymbolAddress((void**)&QKVb,  g_QKV);
    cudaGetSymbolAddress((void**)&Vt,    g_Vt);
    cudaGetSymbolAddress((void**)&ctx,   g_ctx);
    cudaGetSymbolAddress((void**)&res1,  g_res1);
    cudaGetSymbolAddress((void**)&h2,    g_h2);
    cudaGetSymbolAddress((void**)&ff,    g_ff);
    cudaGetSymbolAddress((void**)&WqkvT, g_WqkvT);
    cudaGetSymbolAddress((void**)&bqkv,  g_bqkv);
    cudaGetSymbolAddress((void**)&WoT,   g_WoT);
    cudaGetSymbolAddress((void**)&W1T,   g_W1T);
    cudaGetSymbolAddress((void**)&W2T,   g_W2T);

    cudaFuncSetAttribute(attn_mma, cudaFuncAttributeMaxDynamicSharedMemorySize, ATTN_SMEM);
    cudaFuncSetAttribute(mma_gemm<0,1,1>, cudaFuncAttributeMaxDynamicSharedMemorySize, GSMEM);
    cudaFuncSetAttribute(mma_gemm<1,0,0>, cudaFuncAttributeMaxDynamicSharedMemorySize, GSMEM);
    cudaFuncSetAttribute(mma_gemm<2,1,0>, cudaFuncAttributeMaxDynamicSharedMemorySize, GSMEM);

    // 0: QKV weight transpose
    transpose_wqkv<<<1728, dim3(32, 8)>>>(Wq, Wk, Wv, bq, bk, bv, WqkvT, bqkv);
    // 1: other weight transposes
    transpose_wrest<<<5184, dim3(32, 8)>>>(Wo, W1, W2, WoT, W1T, W2T);
    // 2: LN1 -> fp16
    ln_kernel<<<ML, 256>>>(x, ln1g, ln1b, qin, 1e-6f);
    // 3: fused QKV projection (fp16 out; V part written transposed to Vt)  <- ncu capture
    mma_gemm<0,1,1><<<dim3(QKVS / 128, ML / 128), 128, GSMEM>>>(qin, WqkvT, bqkv, nullptr, QKVb, Vt, DD, QKVS);
    // 4: fp16 tensor-core attention
    attn_mma<<<dim3(LL / 128, HH, BB), 256, ATTN_SMEM>>>(QKVb, Vt, rel, ptab, postag, lexm, ctx);
    // 5: output projection + residual (fp32 out)
    mma_gemm<1,0,0><<<dim3(DD / 128, ML / 128), 128, GSMEM>>>(ctx, WoT, bo, x, res1, nullptr, DD, DD);
    // 6: LN2 -> fp16
    ln_kernel<<<ML, 256>>>(res1, ln2g, ln2b, h2, 1e-5f);
    // 7: FFN up + GELU (fp16 out)
    mma_gemm<2,1,0><<<dim3(FF_ / 128, ML / 128), 128, GSMEM>>>(h2, W1T, b1, nullptr, ff, nullptr, DD, FF_);
    // 8: FFN down + bias + residual -> out (fp32)
    mma_gemm<1,0,0><<<dim3(DD / 128, ML / 128), 128, GSMEM>>>(ff, W2T, b2, res1, out, nullptr, FF_, DD);
}